// round 14
// baseline (speedup 1.0000x reference)
#include <cuda_runtime.h>
#include <cuda_fp16.h>
#include <math.h>
#include <stdint.h>

#define BB 2
#define LL 2048
#define DD 2048
#define HV 32
#define HK 16
#define DK 128
#define DV 128
#define KCONV 4
#define KEY_DIM 2048
#define VAL_DIM 4096
#define CONV_DIM 8192
#define BL (BB*LL)

// fp32 intermediates
__device__ float g_mixed[(size_t)BL * CONV_DIM];
__device__ float g_conv [(size_t)BL * CONV_DIM];
__device__ float g_z    [(size_t)BL * VAL_DIM];
__device__ float g_core [(size_t)BL * VAL_DIM];
__device__ float g_gvals[(size_t)BL * HV];
__device__ float g_beta [(size_t)BL * HV];
__device__ float g_S    [(size_t)HV * BB * 2 * 64 * 128];   // scan state handoff
// fp16 operands
__device__ __half g_hsh   [(size_t)BL * DD];
__device__ __half g_wqkvh [(size_t)CONV_DIM * DD];   // [N][K]
__device__ __half g_wzh   [(size_t)VAL_DIM * DD];    // [N][K]
__device__ __half g_wouth [(size_t)DD * VAL_DIM];    // [N][K]
__device__ __half g_gatedh[(size_t)BL * VAL_DIM];

// ---------------------------------------------------------------------------
// helpers
// ---------------------------------------------------------------------------
__device__ __forceinline__ uint32_t smem_u32(const void* p) {
    uint32_t a;
    asm("{ .reg .u64 t; cvta.to.shared.u64 t, %1; cvt.u32.u64 %0, t; }"
        : "=r"(a) : "l"(p));
    return a;
}
__device__ __forceinline__ void cpa16(uint32_t dst, const void* src) {
    asm volatile("cp.async.cg.shared.global [%0], [%1], 16;\n" :: "r"(dst), "l"(src));
}
#define CP_COMMIT()  asm volatile("cp.async.commit_group;\n")

// ---------------------------------------------------------------------------
// fp16 tensor-core GEMM, ldmatrix + 4-stage cp.async.
// C[M,N] = A[M,K] @ Bt[N,K]^T ; row range starts at row_off.
// CTA tile 128x256, BK=32 halves/stage, 8 warps of 64x64, m16n8k16.
// ---------------------------------------------------------------------------
#define NSTG 4
#define ROWB 80
#define A_BYTES (128 * ROWB)
#define B_BYTES (256 * ROWB)
#define STG_BYTES (A_BYTES + B_BYTES)
#define GEMM_SMEM (NSTG * STG_BYTES) // 122880

__global__ __launch_bounds__(256, 1) void gemm_f16(
    const __half* __restrict__ A, const __half* __restrict__ Bt,
    float* __restrict__ C, int N, int K, int row_off)
{
    extern __shared__ char sm[];
    const uint32_t smb = smem_u32(sm);

    const int tid  = threadIdx.x;
    const int warp = tid >> 5;
    const int lane = tid & 31;
    const int g    = lane >> 2;
    const int t    = lane & 3;

    const int wm = (warp >> 2) * 64;
    const int wn = (warp & 3)  * 64;

    const __half* Ab = A  + (size_t)(row_off + blockIdx.y * 128) * K;
    const __half* Bb = Bt + (size_t)blockIdx.x * 256 * K;

    const uint32_t aOff = (uint32_t)((wm + (lane & 7) + ((lane >> 3) & 1) * 8) * ROWB
                                     + (lane >> 4) * 16);
    const uint32_t bOff = (uint32_t)(A_BYTES
                                     + (wn + (lane & 7) + (lane >> 4) * 8) * ROWB
                                     + ((lane >> 3) & 1) * 16);

    float acc[4][8][4];
    #pragma unroll
    for (int mi = 0; mi < 4; mi++)
        #pragma unroll
        for (int ni = 0; ni < 8; ni++)
            #pragma unroll
            for (int r = 0; r < 4; r++) acc[mi][ni][r] = 0.f;

    const int nt = K >> 5;

    #define LOAD_STAGE(KT, STG) do {                                           \
        const int k0_ = (KT) << 5;                                             \
        const uint32_t sa_ = smb + (uint32_t)(STG) * STG_BYTES;                \
        const uint32_t sb_ = sa_ + A_BYTES;                                    \
        _Pragma("unroll")                                                      \
        for (int i_ = 0; i_ < 2; i_++) {                                       \
            const int idx_ = tid + i_ * 256;                                   \
            const int r_ = idx_ >> 2, ch_ = idx_ & 3;                          \
            cpa16(sa_ + (uint32_t)(r_ * ROWB + ch_ * 16),                      \
                  Ab + (size_t)r_ * K + k0_ + ch_ * 8);                        \
        }                                                                      \
        _Pragma("unroll")                                                      \
        for (int i_ = 0; i_ < 4; i_++) {                                       \
            const int idx_ = tid + i_ * 256;                                   \
            const int r_ = idx_ >> 2, ch_ = idx_ & 3;                          \
            cpa16(sb_ + (uint32_t)(r_ * ROWB + ch_ * 16),                      \
                  Bb + (size_t)r_ * K + k0_ + ch_ * 8);                        \
        }                                                                      \
    } while (0)

    #pragma unroll
    for (int s = 0; s < NSTG - 1; s++) {
        if (s < nt) LOAD_STAGE(s, s);
        CP_COMMIT();
    }

    for (int kt = 0; kt < nt; kt++) {
        asm volatile("cp.async.wait_group %0;\n" :: "n"(NSTG - 2));
        __syncthreads();

        const int pf = kt + NSTG - 1;
        if (pf < nt) LOAD_STAGE(pf, pf % NSTG);
        CP_COMMIT();

        const uint32_t sbase = smb + (uint32_t)(kt % NSTG) * STG_BYTES;

        #pragma unroll
        for (int ks = 0; ks < 2; ks++) {
            uint32_t af[4][4], bf[8][2];
            #pragma unroll
            for (int mi = 0; mi < 4; mi++) {
                const uint32_t addr = sbase + aOff + (uint32_t)(mi * 16 * ROWB + ks * 32);
                asm volatile(
                    "ldmatrix.sync.aligned.m8n8.x4.shared.b16 {%0,%1,%2,%3}, [%4];"
                    : "=r"(af[mi][0]), "=r"(af[mi][1]), "=r"(af[mi][2]), "=r"(af[mi][3])
                    : "r"(addr));
            }
            #pragma unroll
            for (int pr = 0; pr < 4; pr++) {
                const uint32_t addr = sbase + bOff + (uint32_t)(pr * 16 * ROWB + ks * 32);
                asm volatile(
                    "ldmatrix.sync.aligned.m8n8.x4.shared.b16 {%0,%1,%2,%3}, [%4];"
                    : "=r"(bf[2*pr][0]), "=r"(bf[2*pr][1]),
                      "=r"(bf[2*pr+1][0]), "=r"(bf[2*pr+1][1])
                    : "r"(addr));
            }
            #pragma unroll
            for (int mi = 0; mi < 4; mi++)
                #pragma unroll
                for (int ni = 0; ni < 8; ni++) {
                    asm volatile(
                        "mma.sync.aligned.m16n8k16.row.col.f32.f16.f16.f32 "
                        "{%0,%1,%2,%3}, {%4,%5,%6,%7}, {%8,%9}, {%0,%1,%2,%3};"
                        : "+f"(acc[mi][ni][0]), "+f"(acc[mi][ni][1]),
                          "+f"(acc[mi][ni][2]), "+f"(acc[mi][ni][3])
                        : "r"(af[mi][0]), "r"(af[mi][1]), "r"(af[mi][2]), "r"(af[mi][3]),
                          "r"(bf[ni][0]), "r"(bf[ni][1]));
                }
        }
    }

    float* Cblk = C + (size_t)(row_off + blockIdx.y * 128) * N + (size_t)blockIdx.x * 256;
    #pragma unroll
    for (int mi = 0; mi < 4; mi++) {
        #pragma unroll
        for (int ni = 0; ni < 8; ni++) {
            const size_t rr = (size_t)(wm + mi * 16 + g);
            const size_t cc = (size_t)(wn + ni * 8 + 2 * t);
            float2 v0 = make_float2(acc[mi][ni][0], acc[mi][ni][1]);
            float2 v1 = make_float2(acc[mi][ni][2], acc[mi][ni][3]);
            *(float2*)&Cblk[rr * N + cc]       = v0;
            *(float2*)&Cblk[(rr + 8) * N + cc] = v1;
        }
    }
    #undef LOAD_STAGE
}

// ---------------------------------------------------------------------------
// fp32 -> fp16 elementwise
// ---------------------------------------------------------------------------
__global__ __launch_bounds__(256) void f2h_kernel(
    const float* __restrict__ src, __half* __restrict__ dst, int n4)
{
    int i = blockIdx.x * 256 + threadIdx.x;
    if (i >= n4) return;
    float4 v = ((const float4*)src)[i];
    __half2 h0 = __floats2half2_rn(v.x, v.y);
    __half2 h1 = __floats2half2_rn(v.z, v.w);
    uint2 u;
    u.x = *(uint32_t*)&h0;
    u.y = *(uint32_t*)&h1;
    ((uint2*)dst)[i] = u;
}

// ---------------------------------------------------------------------------
// fp32 [R][Nc] -> fp16 transposed [Nc][R]
// ---------------------------------------------------------------------------
__global__ __launch_bounds__(256) void transpose_f2h(
    const float* __restrict__ src, __half* __restrict__ dst, int R, int Nc)
{
    __shared__ float tile[32][33];
    const int x  = blockIdx.x * 32 + threadIdx.x;
    const int y0 = blockIdx.y * 32 + threadIdx.y;
    #pragma unroll
    for (int j = 0; j < 4; j++)
        tile[threadIdx.y + j * 8][threadIdx.x] = src[(size_t)(y0 + j * 8) * Nc + x];
    __syncthreads();
    const int nx  = blockIdx.y * 32 + threadIdx.x;
    const int ny0 = blockIdx.x * 32 + threadIdx.y;
    #pragma unroll
    for (int j = 0; j < 4; j++)
        dst[(size_t)(ny0 + j * 8) * R + nx] =
            __float2half_rn(tile[threadIdx.x][threadIdx.y + j * 8]);
}

// ---------------------------------------------------------------------------
// beta / g projections + activations
// ---------------------------------------------------------------------------
__global__ __launch_bounds__(128) void bg_kernel(
    const float* __restrict__ hs, const float* __restrict__ W_b,
    const float* __restrict__ W_a, const float* __restrict__ dt_bias,
    const float* __restrict__ A_log)
{
    __shared__ float row[DD];
    const int bl  = blockIdx.x;
    const int tid = threadIdx.x;

    for (int i = tid; i < DD; i += 128)
        row[i] = hs[(size_t)bl * DD + i];
    __syncthreads();

    if (tid < 64) {
        const int h = tid & 31;
        const bool isA = tid >= 32;
        const float* W = isA ? W_a : W_b;
        float acc = 0.f;
        #pragma unroll 8
        for (int i = 0; i < DD; i++)
            acc = fmaf(row[i], W[i * HV + h], acc);
        if (isA) {
            float x  = acc + dt_bias[h];
            float sp = (x > 20.f) ? x : log1pf(expf(x));
            g_gvals[(size_t)bl * HV + h] = -expf(A_log[h]) * sp;
        } else {
            g_beta[(size_t)bl * HV + h] = 1.f / (1.f + expf(-acc));
        }
    }
}

// ---------------------------------------------------------------------------
// causal depthwise conv(K=4) + SiLU + l2norm(q,k) + q*DK^-0.5
// v2: 8 timesteps per block (load 11 rows, emit 8).
// grid (64, nbl/8); bl range [bl_base, bl_base + 8*gridDim.y)
// ---------------------------------------------------------------------------
#define TCONV 8
__global__ __launch_bounds__(128) void conv_kernel(
    const float* __restrict__ conv_w, int bl_base)
{
    const int grp = blockIdx.x;
    const int bl0 = bl_base + blockIdx.y * TCONV;
    const int l0  = bl0 & (LL - 1);
    const int tid = threadIdx.x;
    const int c   = grp * 128 + tid;

    const float w0 = conv_w[c * 4 + 0];
    const float w1 = conv_w[c * 4 + 1];
    const float w2 = conv_w[c * 4 + 2];
    const float w3 = conv_w[c * 4 + 3];

    // load rows l0-3 .. l0+7 (11 rows), zero outside sequence start
    float m[TCONV + 3];
    #pragma unroll
    for (int i = 0; i < TCONV + 3; i++) {
        const int l = l0 + i - 3;
        m[i] = (l >= 0) ? g_mixed[(size_t)(bl0 + i - 3) * CONV_DIM + c] : 0.f;
    }

    float s[TCONV], ss[TCONV];
    #pragma unroll
    for (int tt = 0; tt < TCONV; tt++) {
        float acc = m[tt] * w0;
        acc = fmaf(m[tt + 1], w1, acc);
        acc = fmaf(m[tt + 2], w2, acc);
        acc = fmaf(m[tt + 3], w3, acc);
        s[tt] = acc / (1.f + expf(-acc));
        ss[tt] = s[tt] * s[tt];
    }

    if (grp < 32) {
        __shared__ float red[4][TCONV];
        #pragma unroll
        for (int tt = 0; tt < TCONV; tt++)
            #pragma unroll
            for (int o = 16; o; o >>= 1)
                ss[tt] += __shfl_xor_sync(0xffffffffu, ss[tt], o);
        if ((tid & 31) == 0)
            #pragma unroll
            for (int tt = 0; tt < TCONV; tt++)
                red[tid >> 5][tt] = ss[tt];
        __syncthreads();
        #pragma unroll
        for (int tt = 0; tt < TCONV; tt++) {
            float tot = red[0][tt] + red[1][tt] + red[2][tt] + red[3][tt];
            float sc = rsqrtf(tot + 1e-6f);
            if (grp < 16) sc *= 0.08838834764831845f;
            s[tt] *= sc;
        }
    }
    #pragma unroll
    for (int tt = 0; tt < TCONV; tt++)
        g_conv[(size_t)(bl0 + tt) * CONV_DIM + c] = s[tt];
}

// ---------------------------------------------------------------------------
// Gated delta-rule scan, phased: processes t in [t0,t1), state via g_S.
// grid (HV, BB, 2), 128 thr = 64 cols x 2 k-split.
// ---------------------------------------------------------------------------
__global__ __launch_bounds__(128) void scan_kernel(int t0, int t1, int restore)
{
    const int h    = blockIdx.x;
    const int b    = blockIdx.y;
    const int half = blockIdx.z;
    const int tid  = threadIdx.x;
    const int col  = tid & 63;
    const int kh   = tid >> 6;
    const int hk   = h >> 1;

    __shared__ float ksm[128];
    __shared__ float qsm[128];
    __shared__ float pkv[2][64];
    __shared__ float po [2][64];

    const int blkid = (h * BB + b) * 2 + half;
    float* Sg = g_S + (size_t)blkid * 8192;   // layout [j][tid]

    float S[64];
    if (restore) {
        #pragma unroll
        for (int j = 0; j < 64; j++) S[j] = Sg[j * 128 + tid];
    } else {
        #pragma unroll
        for (int j = 0; j < 64; j++) S[j] = 0.f;
    }

    const size_t rowbase = (size_t)b * LL * CONV_DIM;
    const int qc = hk * 128 + tid;
    const int kc = KEY_DIM + hk * 128 + tid;
    const int vc = 2 * KEY_DIM + h * 128 + half * 64 + col;

    // preload t = t0
    {
        const size_t off0 = rowbase + (size_t)t0 * CONV_DIM;
        const int sidx0 = (b * LL + t0) * HV + h;
        ksm[tid] = 0.f; // placate compiler; real values below
        float kn0 = g_conv[off0 + kc];
        float qn0 = g_conv[off0 + qc];
        float vn0 = g_conv[off0 + vc];
        float gn0 = g_gvals[sidx0];
        float bn0 = g_beta[sidx0];
        // stash in registers via loop-carried vars:
        // (fallthrough into loop with these)
        float kn = kn0, qn = qn0, vn = vn0, gn = gn0, bn = bn0;

        for (int t = t0; t < t1; t++) {
            ksm[tid] = kn;
            qsm[tid] = qn;
            const float vt = vn, gt = gn, bt = bn;
            __syncthreads();

            if (t + 1 < t1) {
                const size_t offn = rowbase + (size_t)(t + 1) * CONV_DIM;
                kn = g_conv[offn + kc];
                qn = g_conv[offn + qc];
                vn = g_conv[offn + vc];
                const int sidx = (b * LL + t + 1) * HV + h;
                gn = g_gvals[sidx];
                bn = g_beta[sidx];
            }

            const float eg = expf(gt);
            const float* kp = ksm + kh * 64;
            const float* qp = qsm + kh * 64;

            float kv = 0.f;
            #pragma unroll
            for (int j = 0; j < 64; j++) {
                S[j] *= eg;
                kv = fmaf(kp[j], S[j], kv);
            }
            pkv[kh][col] = kv;
            __syncthreads();

            const float delta = (vt - pkv[0][col] - pkv[1][col]) * bt;

            float o = 0.f;
            #pragma unroll
            for (int j = 0; j < 64; j++) {
                S[j] = fmaf(kp[j], delta, S[j]);
                o = fmaf(qp[j], S[j], o);
            }
            po[kh][col] = o;
            __syncthreads();

            if (kh == 0)
                g_core[((size_t)(b * LL + t)) * VAL_DIM + h * 128 + half * 64 + col]
                    = po[0][col] + po[1][col];
        }
    }

    if (t1 < LL) {
        #pragma unroll
        for (int j = 0; j < 64; j++) Sg[j * 128 + tid] = S[j];
    }
}

// ---------------------------------------------------------------------------
// Gated RMSNorm -> fp16 output for final GEMM
// ---------------------------------------------------------------------------
__global__ __launch_bounds__(128) void gatednorm_kernel(const float* __restrict__ norm_w)
{
    const int h   = blockIdx.x;
    const int bl  = blockIdx.y;
    const int tid = threadIdx.x;
    const size_t idx = (size_t)bl * VAL_DIM + h * 128 + tid;

    float c  = g_core[idx];
    float zz = g_z[idx];
    float gz = zz / (1.f + expf(-zz));
    float x  = c * gz;

    __shared__ float red[4];
    float ss = x * x;
    #pragma unroll
    for (int o = 16; o; o >>= 1)
        ss += __shfl_xor_sync(0xffffffffu, ss, o);
    if ((tid & 31) == 0) red[tid >> 5] = ss;
    __syncthreads();
    float tot  = red[0] + red[1] + red[2] + red[3];
    float mean = tot * (1.f / 128.f);

    g_gatedh[idx] = __float2half_rn(x * rsqrtf(mean + 1e-6f) * norm_w[tid]);
}

// ---------------------------------------------------------------------------
extern "C" void kernel_launch(void* const* d_in, const int* in_sizes, int n_in,
                              void* d_out, int out_size)
{
    const float* hs      = (const float*)d_in[0];
    const float* W_qkv   = (const float*)d_in[1];
    const float* W_z     = (const float*)d_in[2];
    const float* W_b     = (const float*)d_in[3];
    const float* W_a     = (const float*)d_in[4];
    const float* conv_w  = (const float*)d_in[5];
    const float* dt_bias = (const float*)d_in[6];
    const float* A_log   = (const float*)d_in[7];
    const float* norm_w  = (const float*)d_in[8];
    const float* W_out   = (const float*)d_in[9];
    float* out = (float*)d_out;

    float*  mixed_ptr; cudaGetSymbolAddress((void**)&mixed_ptr, g_mixed);
    float*  z_ptr;     cudaGetSymbolAddress((void**)&z_ptr,     g_z);
    __half* hsh;       cudaGetSymbolAddress((void**)&hsh,       g_hsh);
    __half* wqkvh;     cudaGetSymbolAddress((void**)&wqkvh,     g_wqkvh);
    __half* wzh;       cudaGetSymbolAddress((void**)&wzh,       g_wzh);
    __half* wouth;     cudaGetSymbolAddress((void**)&wouth,     g_wouth);
    __half* gatedh;    cudaGetSymbolAddress((void**)&gatedh,    g_gatedh);

    static cudaStream_t s2 = nullptr, s3 = nullptr;
    static cudaEvent_t e0, eBG, eS3, eCONVA, eCONVB, eG2;
    if (s2 == nullptr) {
        cudaStreamCreateWithFlags(&s2, cudaStreamNonBlocking);
        cudaStreamCreateWithFlags(&s3, cudaStreamNonBlocking);
        cudaEventCreateWithFlags(&e0,     cudaEventDisableTiming);
        cudaEventCreateWithFlags(&eBG,    cudaEventDisableTiming);
        cudaEventCreateWithFlags(&eS3,    cudaEventDisableTiming);
        cudaEventCreateWithFlags(&eCONVA, cudaEventDisableTiming);
        cudaEventCreateWithFlags(&eCONVB, cudaEventDisableTiming);
        cudaEventCreateWithFlags(&eG2,    cudaEventDisableTiming);
        cudaFuncSetAttribute(gemm_f16,
            cudaFuncAttributeMaxDynamicSharedMemorySize, GEMM_SMEM);
    }

    const int HLF = LL / 2;   // 1024

    // fork
    cudaEventRecord(e0, 0);
    cudaStreamWaitEvent(s2, e0, 0);
    cudaStreamWaitEvent(s3, e0, 0);

    // s3: independent prep (bg + z/out weight transposes)
    bg_kernel<<<BL, 128, 0, s3>>>(hs, W_b, W_a, dt_bias, A_log);
    cudaEventRecord(eBG, s3);
    transpose_f2h<<<dim3(VAL_DIM / 32, DD / 32), dim3(32, 8), 0, s3>>>(W_z, wzh, DD, VAL_DIM);
    transpose_f2h<<<dim3(DD / 32, VAL_DIM / 32), dim3(32, 8), 0, s3>>>(W_out, wouth, VAL_DIM, DD);
    cudaEventRecord(eS3, s3);

    // main: conversions -> gemm1 phase A (rows t<1024, both batches) -> conv A
    f2h_kernel<<<(BL * DD / 4 + 255) / 256, 256>>>(hs, hsh, BL * DD / 4);
    transpose_f2h<<<dim3(CONV_DIM / 32, DD / 32), dim3(32, 8)>>>(W_qkv, wqkvh, DD, CONV_DIM);
    gemm_f16<<<dim3(CONV_DIM/256, HLF/128), 256, GEMM_SMEM>>>(hsh, wqkvh, mixed_ptr, CONV_DIM, DD, 0);
    gemm_f16<<<dim3(CONV_DIM/256, HLF/128), 256, GEMM_SMEM>>>(hsh, wqkvh, mixed_ptr, CONV_DIM, DD, LL);
    conv_kernel<<<dim3(64, HLF/TCONV), 128>>>(conv_w, 0);
    conv_kernel<<<dim3(64, HLF/TCONV), 128>>>(conv_w, LL);
    cudaEventRecord(eCONVA, 0);

    // s2: gemm1 phase B + conv B + gemm2 (overlaps scan-a / scan-b on main)
    cudaStreamWaitEvent(s2, eCONVA, 0);
    gemm_f16<<<dim3(CONV_DIM/256, HLF/128), 256, GEMM_SMEM, s2>>>(hsh, wqkvh, mixed_ptr, CONV_DIM, DD, HLF);
    gemm_f16<<<dim3(CONV_DIM/256, HLF/128), 256, GEMM_SMEM, s2>>>(hsh, wqkvh, mixed_ptr, CONV_DIM, DD, LL + HLF);
    conv_kernel<<<dim3(64, HLF/TCONV), 128, 0, s2>>>(conv_w, HLF);
    conv_kernel<<<dim3(64, HLF/TCONV), 128, 0, s2>>>(conv_w, LL + HLF);
    cudaEventRecord(eCONVB, s2);
    cudaStreamWaitEvent(s2, eS3, 0);
    gemm_f16<<<dim3(VAL_DIM/256, BL/128), 256, GEMM_SMEM, s2>>>(hsh, wzh, z_ptr, VAL_DIM, DD, 0);
    cudaEventRecord(eG2, s2);

    // main: scan phase A (t<1024), then phase B after conv B
    cudaStreamWaitEvent(0, eBG, 0);
    scan_kernel<<<dim3(HV, BB, 2), 128>>>(0, HLF, 0);
    cudaStreamWaitEvent(0, eCONVB, 0);
    scan_kernel<<<dim3(HV, BB, 2), 128>>>(HLF, LL, 1);

    // join: norm needs z (eG2), gemm3 needs wouth (eS3, already waited via s2 chain)
    cudaStreamWaitEvent(0, eG2, 0);
    gatednorm_kernel<<<dim3(HV, BL), 128>>>(norm_w);
    gemm_f16<<<dim3(DD/256, BL/128), 256, GEMM_SMEM>>>(gatedh, wouth, out, DD, VAL_DIM, 0);
}